// round 12
// baseline (speedup 1.0000x reference)
#include <cuda_runtime.h>

#define FULLMASK 0xffffffffu

namespace {
constexpr int H = 32, T = 512, D = 6, B = 4096;
constexpr int NB = 4;                        // samples per warp
constexpr int NJOBS = B / NB;                // 1024 warp-jobs
constexpr int WARPS = 7;
constexpr int TPB = WARPS * 32;              // 224
constexpr int GRID = 148;                    // one block per SM
constexpr int KH0 = 6, KI1 = 38, KH1 = 70;   // k-row offsets in weight array
constexpr int SW_FLOATS = 102 * 128;         // 13056
constexpr int NC = 24;                       // register-cached k-rows (KH1 k=8..31)
constexpr int XP = 8;                        // x staging stride/sample
constexpr int HP = 32;                       // h staging stride/sample
constexpr int STG_X0 = 0;                    // x buffer 0: 32 floats
constexpr int STG_X1 = 32;                   // x buffer 1: 32 floats
constexpr int STG_H0 = 64;                   // h0: 4*32 = 128
constexpr int STG_H1 = 192;                  // h1: 4*32 = 128
constexpr int STG_SZ = 320;                  // per-warp staging floats
constexpr int SMEM_FLOATS = SW_FLOATS + WARPS * STG_SZ;  // 15296
constexpr int SMEM_BYTES = SMEM_FLOATS * 4;              // 61184
}

// weights [k][128], row r = 4*unit + gate, pre-scaled by -log2(e) (-2log2(e) for g gate)
__device__ __align__(16) float g_W[SW_FLOATS];
__device__ __align__(16) float g_B[256];     // [0:128) layer0, [128:256) layer1

__global__ void prep_kernel(const float* __restrict__ Wih0, const float* __restrict__ Whh0,
                            const float* __restrict__ bih0, const float* __restrict__ bhh0,
                            const float* __restrict__ Wih1, const float* __restrict__ Whh1,
                            const float* __restrict__ bih1, const float* __restrict__ bhh1) {
    int r = threadIdx.x;
    if (r >= 128) return;
    int u = r >> 2;
    int g = r & 3;
    int orig = g * H + u;                    // original gate-major row
    const float sc = (g == 2) ? -2.8853900817779268f : -1.4426950408889634f;
    g_B[r]       = (bih0[orig] + bhh0[orig]) * sc;
    g_B[128 + r] = (bih1[orig] + bhh1[orig]) * sc;
#pragma unroll
    for (int k = 0; k < D; k++) g_W[k * 128 + r] = Wih0[orig * D + k] * sc;
#pragma unroll
    for (int k = 0; k < H; k++) g_W[(KH0 + k) * 128 + r] = Whh0[orig * H + k] * sc;
#pragma unroll
    for (int k = 0; k < H; k++) g_W[(KI1 + k) * 128 + r] = Wih1[orig * H + k] * sc;
#pragma unroll
    for (int k = 0; k < H; k++) g_W[(KH1 + k) * 128 + r] = Whh1[orig * H + k] * sc;
}

__device__ __forceinline__ unsigned long long dup2(float v) {
    unsigned long long r;
    asm("mov.b64 %0, {%1, %1};" : "=l"(r) : "f"(v));
    return r;
}
__device__ __forceinline__ void fma2(unsigned long long& acc, unsigned long long a,
                                     unsigned long long b) {
    asm("fma.rn.f32x2 %0, %1, %2, %0;" : "+l"(acc) : "l"(a), "l"(b));
}

// returns 1/(1+2^s)  (= sigmoid(a) when s = -log2(e)*a)
__device__ __forceinline__ float sig2(float s) {
    float e;
    asm("ex2.approx.ftz.f32 %0, %1;" : "=f"(e) : "f"(s));
    float r;
    asm("rcp.approx.ftz.f32 %0, %1;" : "=f"(r) : "f"(1.0f + e));
    return r;
}

__global__ void __launch_bounds__(TPB, 1)
lstm_kernel(const float* __restrict__ x,
            const float* __restrict__ gamma,
            const float* __restrict__ beta,
            float* __restrict__ out) {
    extern __shared__ float smem[];

    // cooperative copy of pre-permuted, pre-scaled weights into smem
    {
        const float4* src = (const float4*)g_W;
        float4* dst = (float4*)smem;
        for (int i = threadIdx.x; i < SW_FLOATS / 4; i += TPB) dst[i] = src[i];
    }
    const int w = threadIdx.x >> 5;
    const int lane = threadIdx.x & 31;       // lane = hidden unit
    float* stg = smem + SW_FLOATS + w * STG_SZ;
    for (int i = lane; i < STG_SZ; i += 32) stg[i] = 0.0f;   // h0/h1 start at zero
    __syncthreads();

    const int job = w * GRID + (int)blockIdx.x;  // balanced across 148 SMs
    if (job >= NJOBS) return;                    // only __syncwarp below: safe
    const int sBase = job * NB;

    // biases (i,f | g,o packed) stay in registers for the whole sequence
    const ulonglong2 bias0 = *reinterpret_cast<const ulonglong2*>(&g_B[4 * lane]);
    const ulonglong2 bias1 = *reinterpret_cast<const ulonglong2*>(&g_B[128 + 4 * lane]);

    // register-cached weights: KH1 rows k = 8..31 (24 rows x 16B per lane)
    ulonglong2 wc[NC];
#pragma unroll
    for (int i = 0; i < NC; i++)
        wc[i] = *(const ulonglong2*)&smem[(KH1 + 8 + i) * 128 + 4 * lane];

    // x streaming: 24 values/step; lanes 0..23 carry one (sample, dim) each
    const float* xb = x + (size_t)sBase * (T * D);
    const int s0 = lane / 6, d0 = lane - s0 * 6;
    const bool xact = lane < 24;
    const float* xp0 = xb + (size_t)s0 * (T * D) + d0;
    const int xo = s0 * XP + d0;

    float c0[NB], c1[NB];
#pragma unroll
    for (int s = 0; s < NB; s++) { c0[s] = 0.0f; c1[s] = 0.0f; }

    unsigned long long aIF0[NB], aGO0[NB];   // layer-0 accumulators
    unsigned long long aIF1[NB], aGO1[NB];   // layer-1 accumulators

#define CHUNK4(AIF, AGO, KB, KC, SH, STRIDE)                                           \
    {                                                                                  \
        const ulonglong2 w0 = *(const ulonglong2*)&smem[((KB) + (KC)) * 128 + 4 * lane]; \
        const ulonglong2 w1 = *(const ulonglong2*)&smem[((KB) + (KC) + 1) * 128 + 4 * lane]; \
        const ulonglong2 w2 = *(const ulonglong2*)&smem[((KB) + (KC) + 2) * 128 + 4 * lane]; \
        const ulonglong2 w3 = *(const ulonglong2*)&smem[((KB) + (KC) + 3) * 128 + 4 * lane]; \
        _Pragma("unroll") for (int s = 0; s < NB; s++) {                               \
            const float4 v = *(const float4*)&stg[(SH) + s * (STRIDE) + (KC)];         \
            const unsigned long long e0 = dup2(v.x);                                   \
            const unsigned long long e1 = dup2(v.y);                                   \
            const unsigned long long e2 = dup2(v.z);                                   \
            const unsigned long long e3 = dup2(v.w);                                   \
            fma2(AIF[s], e0, w0.x); fma2(AGO[s], e0, w0.y);                            \
            fma2(AIF[s], e1, w1.x); fma2(AGO[s], e1, w1.y);                            \
            fma2(AIF[s], e2, w2.x); fma2(AGO[s], e2, w2.y);                            \
            fma2(AIF[s], e3, w3.x); fma2(AGO[s], e3, w3.y);                            \
        }                                                                              \
    }

#define CHUNK4R(AIF, AGO, I0, KC, SH, STRIDE)                                          \
    {                                                                                  \
        _Pragma("unroll") for (int s = 0; s < NB; s++) {                               \
            const float4 v = *(const float4*)&stg[(SH) + s * (STRIDE) + (KC)];         \
            const unsigned long long e0 = dup2(v.x);                                   \
            const unsigned long long e1 = dup2(v.y);                                   \
            const unsigned long long e2 = dup2(v.z);                                   \
            const unsigned long long e3 = dup2(v.w);                                   \
            fma2(AIF[s], e0, wc[(I0)].x);     fma2(AGO[s], e0, wc[(I0)].y);            \
            fma2(AIF[s], e1, wc[(I0) + 1].x); fma2(AGO[s], e1, wc[(I0) + 1].y);        \
            fma2(AIF[s], e2, wc[(I0) + 2].x); fma2(AGO[s], e2, wc[(I0) + 2].y);        \
            fma2(AIF[s], e3, wc[(I0) + 3].x); fma2(AGO[s], e3, wc[(I0) + 3].y);        \
        }                                                                              \
    }

#define CHUNK2(AIF, AGO, KB, KC, SH, STRIDE)                                           \
    {                                                                                  \
        const ulonglong2 w0 = *(const ulonglong2*)&smem[((KB) + (KC)) * 128 + 4 * lane]; \
        const ulonglong2 w1 = *(const ulonglong2*)&smem[((KB) + (KC) + 1) * 128 + 4 * lane]; \
        _Pragma("unroll") for (int s = 0; s < NB; s++) {                               \
            const float2 v = *(const float2*)&stg[(SH) + s * (STRIDE) + (KC)];         \
            const unsigned long long e0 = dup2(v.x);                                   \
            const unsigned long long e1 = dup2(v.y);                                   \
            fma2(AIF[s], e0, w0.x); fma2(AGO[s], e0, w0.y);                            \
            fma2(AIF[s], e1, w1.x); fma2(AGO[s], e1, w1.y);                            \
        }                                                                              \
    }

#define ACT(AIF, AGO, CC, SH)                                                          \
    {                                                                                  \
        _Pragma("unroll") for (int s = 0; s < NB; s++) {                               \
            float si, sf, sg, so;                                                      \
            asm("mov.b64 {%0,%1}, %2;" : "=f"(si), "=f"(sf) : "l"(AIF[s]));            \
            asm("mov.b64 {%0,%1}, %2;" : "=f"(sg), "=f"(so) : "l"(AGO[s]));            \
            const float iv = sig2(si);                                                 \
            const float fv = sig2(sf);                                                 \
            const float ov = sig2(so);                                                 \
            const float gt = fmaf(2.0f, sig2(sg), -1.0f);                              \
            const float c = fmaf(fv, CC[s], iv * gt);                                  \
            CC[s] = c;                                                                 \
            const float tc = fmaf(2.0f, sig2(c * -2.8853900817779268f), -1.0f);        \
            stg[(SH) + s * HP + lane] = ov * tc;                                       \
        }                                                                              \
    }

#define INIT(AIF, AGO, BIAS)                                                           \
    _Pragma("unroll") for (int s = 0; s < NB; s++) { AIF[s] = (BIAS).x; AGO[s] = (BIAS).y; }

    // ---------------- prolog: x(0) published, layer-0 gemm of step 0 ----------
    float xa = xact ? xp0[0] : 0.0f;                       // x(0)
    if (xact) stg[STG_X0 + xo] = xa;
    __syncwarp();
    xa = xact ? xp0[(size_t)((T > 1) ? 1 : 0) * D] : 0.0f; // x(1)
    INIT(aIF0, aGO0, bias0);
    CHUNK4(aIF0, aGO0, 0, 0, STG_X0, XP);
    CHUNK2(aIF0, aGO0, 0, 4, STG_X0, XP);
#pragma unroll
    for (int kc = 0; kc < H; kc += 4) CHUNK4(aIF0, aGO0, KH0, kc, STG_H0, HP);
    if (xact) stg[STG_X1 + xo] = xa;                       // x(1) -> buf1
    xa = xact ? xp0[(size_t)((T > 2) ? 2 : T - 1) * D] : 0.0f;   // x(2)

    // ---------------- main loop: 2 syncs/step, ACT blocks overlapped ----------
    for (int t = 0; t < T; t++) {
        __syncwarp();   // sync1: h1(t-1) + x buffers visible; block-A reads done

        // ---- B: ACT0(t) interleaved with Whh1 . h1(t-1) ----
        INIT(aIF1, aGO1, bias1);
        CHUNK4(aIF1, aGO1, KH1, 0, STG_H1, HP);            // k 0..7 from smem
        CHUNK4(aIF1, aGO1, KH1, 4, STG_H1, HP);
        ACT(aIF0, aGO0, c0, STG_H0);                       // writes h0(t)
#pragma unroll
        for (int kc = 8; kc < H; kc += 4)                  // k 8..31 from registers
            CHUNK4R(aIF1, aGO1, kc - 8, kc, STG_H1, HP);

        __syncwarp();   // sync2: h0(t) visible; h1(t-1) reads done

        // ---- C: Wih1 . h0(t) ----
#pragma unroll
        for (int kc = 0; kc < H; kc += 4) CHUNK4(aIF1, aGO1, KI1, kc, STG_H0, HP);

        // ---- A(t+1): ACT1(t) interleaved with layer-0 gemm of step t+1 ----
        const int rdBuf = ((t + 1) & 1) ? STG_X1 : STG_X0; // holds x(t+1)
        const int wrBuf = ((t + 1) & 1) ? STG_X0 : STG_X1; // gets x(t+2)
        INIT(aIF0, aGO0, bias0);
        CHUNK4(aIF0, aGO0, 0, 0, rdBuf, XP);
        CHUNK2(aIF0, aGO0, 0, 4, rdBuf, XP);
        ACT(aIF1, aGO1, c1, STG_H1);                       // writes h1(t)
#pragma unroll
        for (int kc = 0; kc < H; kc += 4) CHUNK4(aIF0, aGO0, KH0, kc, STG_H0, HP);
        if (xact) stg[wrBuf + xo] = xa;                    // publish x(t+2)
        const int tn = (t + 3 < T) ? t + 3 : T - 1;
        if (xact) xa = xp0[(size_t)tn * D];
    }
    __syncwarp();       // h1(T-1) visible for LayerNorm

    // ---------------- LayerNorm over H=32 (lane = hidden unit) ----------------
    const float gam = gamma[lane];
    const float bet = beta[lane];
#pragma unroll
    for (int s = 0; s < NB; s++) {
        const float v = stg[STG_H1 + s * HP + lane];
        float sum = v;
#pragma unroll
        for (int off = 16; off > 0; off >>= 1) sum += __shfl_xor_sync(FULLMASK, sum, off);
        const float mu = sum * (1.0f / 32.0f);
        const float dd = v - mu;
        float sq = dd * dd;
#pragma unroll
        for (int off = 16; off > 0; off >>= 1) sq += __shfl_xor_sync(FULLMASK, sq, off);
        const float var = sq * (1.0f / 32.0f);
        out[(size_t)(sBase + s) * H + lane] = fmaf(dd * rsqrtf(var + 1e-5f), gam, bet);
    }
#undef CHUNK4
#undef CHUNK4R
#undef CHUNK2
#undef ACT
#undef INIT
}

extern "C" void kernel_launch(void* const* d_in, const int* in_sizes, int n_in,
                              void* d_out, int out_size) {
    const float* x    = (const float*)d_in[0];
    const float* Wih0 = (const float*)d_in[1];
    const float* Whh0 = (const float*)d_in[2];
    const float* bih0 = (const float*)d_in[3];
    const float* bhh0 = (const float*)d_in[4];
    const float* Wih1 = (const float*)d_in[5];
    const float* Whh1 = (const float*)d_in[6];
    const float* bih1 = (const float*)d_in[7];
    const float* bhh1 = (const float*)d_in[8];
    const float* gam  = (const float*)d_in[9];
    const float* bet  = (const float*)d_in[10];
    float* out = (float*)d_out;

    cudaFuncSetAttribute(lstm_kernel, cudaFuncAttributeMaxDynamicSharedMemorySize, SMEM_BYTES);
    prep_kernel<<<1, 128>>>(Wih0, Whh0, bih0, bhh0, Wih1, Whh1, bih1, bhh1);
    lstm_kernel<<<GRID, TPB, SMEM_BYTES>>>(x, gam, bet, out);
}

// round 14
// speedup vs baseline: 1.0240x; 1.0240x over previous
#include <cuda_runtime.h>

#define FULLMASK 0xffffffffu

namespace {
constexpr int H = 32, T = 512, D = 6, B = 4096;
constexpr int NB = 4;                        // samples per warp
constexpr int NJOBS = B / NB;                // 1024 warp-jobs
constexpr int WARPS = 7;
constexpr int TPB = WARPS * 32;              // 224
constexpr int GRID = 148;                    // one block per SM
constexpr int KH0 = 6, KI1 = 38, KH1 = 70;   // k-row offsets in weight array
constexpr int SW_FLOATS = 102 * 128;         // 13056
constexpr int NC = 32;                       // register-cached k-rows (ALL of KH1)
constexpr int XP = 8;                        // x staging stride/sample
constexpr int HP = 32;                       // h staging stride/sample (undup)
constexpr int STG_X = 0;                     // x: 4*8 = 32 floats
constexpr int STG_H0 = 32;                   // h0: 4*32 = 128
constexpr int STG_H1 = 160;                  // h1: 4*32 = 128
constexpr int STG_SZ = 288;                  // per-warp staging floats
constexpr int SMEM_FLOATS = SW_FLOATS + WARPS * STG_SZ;  // 15072
constexpr int SMEM_BYTES = SMEM_FLOATS * 4;              // 60288
}

// weights [k][128], row r = 4*unit + gate, pre-scaled by -log2(e) (-2log2(e) for g gate)
__device__ __align__(16) float g_W[SW_FLOATS];
__device__ __align__(16) float g_B[256];     // [0:128) layer0, [128:256) layer1

__global__ void prep_kernel(const float* __restrict__ Wih0, const float* __restrict__ Whh0,
                            const float* __restrict__ bih0, const float* __restrict__ bhh0,
                            const float* __restrict__ Wih1, const float* __restrict__ Whh1,
                            const float* __restrict__ bih1, const float* __restrict__ bhh1) {
    int r = threadIdx.x;
    if (r >= 128) return;
    int u = r >> 2;
    int g = r & 3;
    int orig = g * H + u;                    // original gate-major row
    const float sc = (g == 2) ? -2.8853900817779268f : -1.4426950408889634f;
    g_B[r]       = (bih0[orig] + bhh0[orig]) * sc;
    g_B[128 + r] = (bih1[orig] + bhh1[orig]) * sc;
#pragma unroll
    for (int k = 0; k < D; k++) g_W[k * 128 + r] = Wih0[orig * D + k] * sc;
#pragma unroll
    for (int k = 0; k < H; k++) g_W[(KH0 + k) * 128 + r] = Whh0[orig * H + k] * sc;
#pragma unroll
    for (int k = 0; k < H; k++) g_W[(KI1 + k) * 128 + r] = Wih1[orig * H + k] * sc;
#pragma unroll
    for (int k = 0; k < H; k++) g_W[(KH1 + k) * 128 + r] = Whh1[orig * H + k] * sc;
}

__device__ __forceinline__ unsigned long long dup2(float v) {
    unsigned long long r;
    asm("mov.b64 %0, {%1, %1};" : "=l"(r) : "f"(v));
    return r;
}
__device__ __forceinline__ void fma2(unsigned long long& acc, unsigned long long a,
                                     unsigned long long b) {
    asm("fma.rn.f32x2 %0, %1, %2, %0;" : "+l"(acc) : "l"(a), "l"(b));
}

// returns 1/(1+2^s)  (= sigmoid(a) when s = -log2(e)*a)
__device__ __forceinline__ float sig2(float s) {
    float e;
    asm("ex2.approx.ftz.f32 %0, %1;" : "=f"(e) : "f"(s));
    float r;
    asm("rcp.approx.ftz.f32 %0, %1;" : "=f"(r) : "f"(1.0f + e));
    return r;
}

__global__ void __launch_bounds__(TPB, 1)
lstm_kernel(const float* __restrict__ x,
            const float* __restrict__ gamma,
            const float* __restrict__ beta,
            float* __restrict__ out) {
    extern __shared__ float smem[];

    // cooperative copy of pre-permuted, pre-scaled weights into smem
    {
        const float4* src = (const float4*)g_W;
        float4* dst = (float4*)smem;
        for (int i = threadIdx.x; i < SW_FLOATS / 4; i += TPB) dst[i] = src[i];
    }
    const int w = threadIdx.x >> 5;
    const int lane = threadIdx.x & 31;       // lane = hidden unit
    float* stg = smem + SW_FLOATS + w * STG_SZ;
    for (int i = lane; i < STG_SZ; i += 32) stg[i] = 0.0f;   // h0/h1 start at zero
    __syncthreads();

    const int job = w * GRID + (int)blockIdx.x;  // balanced across 148 SMs
    if (job >= NJOBS) return;                    // only __syncwarp below: safe
    const int sBase = job * NB;

    // biases (i,f | g,o packed) stay in registers for the whole sequence
    const ulonglong2 bias0 = *reinterpret_cast<const ulonglong2*>(&g_B[4 * lane]);
    const ulonglong2 bias1 = *reinterpret_cast<const ulonglong2*>(&g_B[128 + 4 * lane]);

    // register-cached weights: ALL 32 KH1 rows (32 x 16B per lane)
    ulonglong2 wc[NC];
#pragma unroll
    for (int i = 0; i < NC; i++)
        wc[i] = *(const ulonglong2*)&smem[(KH1 + i) * 128 + 4 * lane];

    // x streaming: 24 values/step; lanes 0..23 carry one (sample, dim) each
    const float* xb = x + (size_t)sBase * (T * D);
    const int s0 = lane / 6, d0 = lane - s0 * 6;
    const bool xact = lane < 24;
    const float* xp0 = xb + (size_t)s0 * (T * D) + d0;
    const int xo0 = STG_X + s0 * XP + d0;
    float xa = xact ? xp0[0] : 0.0f;

    float c0[NB], c1[NB];
#pragma unroll
    for (int s = 0; s < NB; s++) { c0[s] = 0.0f; c1[s] = 0.0f; }

    unsigned long long aIF[NB], aGO[NB];

    // 4-k chunk, weights from smem
#define CHUNK4(KB, KC, SH, STRIDE)                                                     \
    {                                                                                  \
        const ulonglong2 w0 = *(const ulonglong2*)&smem[((KB) + (KC)) * 128 + 4 * lane]; \
        const ulonglong2 w1 = *(const ulonglong2*)&smem[((KB) + (KC) + 1) * 128 + 4 * lane]; \
        const ulonglong2 w2 = *(const ulonglong2*)&smem[((KB) + (KC) + 2) * 128 + 4 * lane]; \
        const ulonglong2 w3 = *(const ulonglong2*)&smem[((KB) + (KC) + 3) * 128 + 4 * lane]; \
        _Pragma("unroll") for (int s = 0; s < NB; s++) {                               \
            const float4 v = *(const float4*)&stg[(SH) + s * (STRIDE) + (KC)];         \
            const unsigned long long e0 = dup2(v.x);                                   \
            const unsigned long long e1 = dup2(v.y);                                   \
            const unsigned long long e2 = dup2(v.z);                                   \
            const unsigned long long e3 = dup2(v.w);                                   \
            fma2(aIF[s], e0, w0.x); fma2(aGO[s], e0, w0.y);                            \
            fma2(aIF[s], e1, w1.x); fma2(aGO[s], e1, w1.y);                            \
            fma2(aIF[s], e2, w2.x); fma2(aGO[s], e2, w2.y);                            \
            fma2(aIF[s], e3, w3.x); fma2(aGO[s], e3, w3.y);                            \
        }                                                                              \
    }

    // 4-k chunk, weights from register cache wc[I0..I0+3], broadcasts from smem
#define CHUNK4R(I0, KC, SH, STRIDE)                                                    \
    {                                                                                  \
        _Pragma("unroll") for (int s = 0; s < NB; s++) {                               \
            const float4 v = *(const float4*)&stg[(SH) + s * (STRIDE) + (KC)];         \
            const unsigned long long e0 = dup2(v.x);                                   \
            const unsigned long long e1 = dup2(v.y);                                   \
            const unsigned long long e2 = dup2(v.z);                                   \
            const unsigned long long e3 = dup2(v.w);                                   \
            fma2(aIF[s], e0, wc[(I0)].x);     fma2(aGO[s], e0, wc[(I0)].y);            \
            fma2(aIF[s], e1, wc[(I0) + 1].x); fma2(aGO[s], e1, wc[(I0) + 1].y);        \
            fma2(aIF[s], e2, wc[(I0) + 2].x); fma2(aGO[s], e2, wc[(I0) + 2].y);        \
            fma2(aIF[s], e3, wc[(I0) + 3].x); fma2(aGO[s], e3, wc[(I0) + 3].y);        \
        }                                                                              \
    }

#define CHUNK2(KB, KC, SH, STRIDE)                                                     \
    {                                                                                  \
        const ulonglong2 w0 = *(const ulonglong2*)&smem[((KB) + (KC)) * 128 + 4 * lane]; \
        const ulonglong2 w1 = *(const ulonglong2*)&smem[((KB) + (KC) + 1) * 128 + 4 * lane]; \
        _Pragma("unroll") for (int s = 0; s < NB; s++) {                               \
            const float2 v = *(const float2*)&stg[(SH) + s * (STRIDE) + (KC)];         \
            const unsigned long long e0 = dup2(v.x);                                   \
            const unsigned long long e1 = dup2(v.y);                                   \
            fma2(aIF[s], e0, w0.x); fma2(aGO[s], e0, w0.y);                            \
            fma2(aIF[s], e1, w1.x); fma2(aGO[s], e1, w1.y);                            \
        }                                                                              \
    }

    // activation + undup store of h (lane = unit): 1 STS.32 per sample
#define ACT(CC, SH)                                                                    \
    {                                                                                  \
        _Pragma("unroll") for (int s = 0; s < NB; s++) {                               \
            float si, sf, sg, so;                                                      \
            asm("mov.b64 {%0,%1}, %2;" : "=f"(si), "=f"(sf) : "l"(aIF[s]));            \
            asm("mov.b64 {%0,%1}, %2;" : "=f"(sg), "=f"(so) : "l"(aGO[s]));            \
            const float iv = sig2(si);                                                 \
            const float fv = sig2(sf);                                                 \
            const float ov = sig2(so);                                                 \
            const float gt = fmaf(2.0f, sig2(sg), -1.0f);                              \
            const float c = fmaf(fv, CC[s], iv * gt);                                  \
            CC[s] = c;                                                                 \
            const float tc = fmaf(2.0f, sig2(c * -2.8853900817779268f), -1.0f);        \
            stg[(SH) + s * HP + lane] = ov * tc;                                       \
        }                                                                              \
    }

    for (int t = 0; t < T; t++) {
        // publish x(t), then prefetch x(t+1)
        if (xact) stg[xo0] = xa;
        __syncwarp();
        const int tn = (t + 1 < T) ? t + 1 : t;
        if (xact) xa = xp0[(size_t)tn * D];

        // ---------------- layer 0: x (6 k) + h0 (32 k) ----------------
#pragma unroll
        for (int s = 0; s < NB; s++) { aIF[s] = bias0.x; aGO[s] = bias0.y; }
        CHUNK4(0, 0, STG_X, XP);
        CHUNK2(0, 4, STG_X, XP);
#pragma unroll
        for (int kc = 0; kc < H; kc += 4) CHUNK4(KH0, kc, STG_H0, HP);
        __syncwarp();
        ACT(c0, STG_H0);
        __syncwarp();

        // ---------------- layer 1: h0 (32 k) + h1 (32 k) ----------------
#pragma unroll
        for (int s = 0; s < NB; s++) { aIF[s] = bias1.x; aGO[s] = bias1.y; }
#pragma unroll
        for (int kc = 0; kc < H; kc += 4) CHUNK4(KI1, kc, STG_H0, HP);
#pragma unroll
        for (int kc = 0; kc < H; kc += 4)                 // all KH1 from registers
            CHUNK4R(kc, kc, STG_H1, HP);
        __syncwarp();
        ACT(c1, STG_H1);
        __syncwarp();
    }

    // ---------------- LayerNorm over H=32 (lane = hidden unit) ----------------
    const float gam = gamma[lane];
    const float bet = beta[lane];
#pragma unroll
    for (int s = 0; s < NB; s++) {
        const float v = stg[STG_H1 + s * HP + lane];
        float sum = v;
#pragma unroll
        for (int off = 16; off > 0; off >>= 1) sum += __shfl_xor_sync(FULLMASK, sum, off);
        const float mu = sum * (1.0f / 32.0f);
        const float dd = v - mu;
        float sq = dd * dd;
#pragma unroll
        for (int off = 16; off > 0; off >>= 1) sq += __shfl_xor_sync(FULLMASK, sq, off);
        const float var = sq * (1.0f / 32.0f);
        out[(size_t)(sBase + s) * H + lane] = fmaf(dd * rsqrtf(var + 1e-5f), gam, bet);
    }
#undef CHUNK4
#undef CHUNK4R
#undef CHUNK2
#undef ACT
}

extern "C" void kernel_launch(void* const* d_in, const int* in_sizes, int n_in,
                              void* d_out, int out_size) {
    const float* x    = (const float*)d_in[0];
    const float* Wih0 = (const float*)d_in[1];
    const float* Whh0 = (const float*)d_in[2];
    const float* bih0 = (const float*)d_in[3];
    const float* bhh0 = (const float*)d_in[4];
    const float* Wih1 = (const float*)d_in[5];
    const float* Whh1 = (const float*)d_in[6];
    const float* bih1 = (const float*)d_in[7];
    const float* bhh1 = (const float*)d_in[8];
    const float* gam  = (const float*)d_in[9];
    const float* bet  = (const float*)d_in[10];
    float* out = (float*)d_out;

    cudaFuncSetAttribute(lstm_kernel, cudaFuncAttributeMaxDynamicSharedMemorySize, SMEM_BYTES);
    prep_kernel<<<1, 128>>>(Wih0, Whh0, bih0, bhh0, Wih1, Whh1, bih1, bhh1);
    lstm_kernel<<<GRID, TPB, SMEM_BYTES>>>(x, gam, bet, out);
}

// round 15
// speedup vs baseline: 1.1106x; 1.0845x over previous
#include <cuda_runtime.h>

#define FULLMASK 0xffffffffu

namespace {
constexpr int H = 32, T = 512, D = 6, B = 4096;
constexpr int NB = 4;                        // samples per warp
constexpr int NJOBS = B / NB;                // 1024 warp-jobs
constexpr int WARPS = 7;
constexpr int TPB = WARPS * 32;              // 224
constexpr int GRID = 148;                    // one block per SM
constexpr int KH0 = 6, KI1 = 38, KH1 = 70;   // k-row offsets in weight array
constexpr int SW_FLOATS = 102 * 128;         // 13056
constexpr int NC = 28;                       // register-cached k-rows (KH1 k=4..31)
constexpr int XP = 8;                        // x staging stride/sample
constexpr int HP = 32;                       // h staging stride/sample (undup)
constexpr int STG_X = 0;                     // x: 4*8 = 32 floats
constexpr int STG_H0 = 32;                   // h0: 4*32 = 128
constexpr int STG_H1 = 160;                  // h1: 4*32 = 128
constexpr int STG_SZ = 288;                  // per-warp staging floats
constexpr int SMEM_FLOATS = SW_FLOATS + WARPS * STG_SZ;  // 15072
constexpr int SMEM_BYTES = SMEM_FLOATS * 4;              // 60288
}

// weights [k][128], row r = 4*unit + gate.
// Per-gate prescale: i,f,o rows by -log2(e) (feeds 1/(1+2^s) sigmoid);
// g row by 1.0 (feeds tanh.approx directly).
__device__ __align__(16) float g_W[SW_FLOATS];
__device__ __align__(16) float g_B[256];     // [0:128) layer0, [128:256) layer1

__global__ void prep_kernel(const float* __restrict__ Wih0, const float* __restrict__ Whh0,
                            const float* __restrict__ bih0, const float* __restrict__ bhh0,
                            const float* __restrict__ Wih1, const float* __restrict__ Whh1,
                            const float* __restrict__ bih1, const float* __restrict__ bhh1) {
    int r = threadIdx.x;
    if (r >= 128) return;
    int u = r >> 2;
    int g = r & 3;
    int orig = g * H + u;                    // original gate-major row
    const float sc = (g == 2) ? 1.0f : -1.4426950408889634f;
    g_B[r]       = (bih0[orig] + bhh0[orig]) * sc;
    g_B[128 + r] = (bih1[orig] + bhh1[orig]) * sc;
#pragma unroll
    for (int k = 0; k < D; k++) g_W[k * 128 + r] = Wih0[orig * D + k] * sc;
#pragma unroll
    for (int k = 0; k < H; k++) g_W[(KH0 + k) * 128 + r] = Whh0[orig * H + k] * sc;
#pragma unroll
    for (int k = 0; k < H; k++) g_W[(KI1 + k) * 128 + r] = Wih1[orig * H + k] * sc;
#pragma unroll
    for (int k = 0; k < H; k++) g_W[(KH1 + k) * 128 + r] = Whh1[orig * H + k] * sc;
}

__device__ __forceinline__ unsigned long long dup2(float v) {
    unsigned long long r;
    asm("mov.b64 %0, {%1, %1};" : "=l"(r) : "f"(v));
    return r;
}
__device__ __forceinline__ void fma2(unsigned long long& acc, unsigned long long a,
                                     unsigned long long b) {
    asm("fma.rn.f32x2 %0, %1, %2, %0;" : "+l"(acc) : "l"(a), "l"(b));
}

// returns 1/(1+2^s)  (= sigmoid(a) when s = -log2(e)*a)
__device__ __forceinline__ float sig2(float s) {
    float e;
    asm("ex2.approx.ftz.f32 %0, %1;" : "=f"(e) : "f"(s));
    float r;
    asm("rcp.approx.ftz.f32 %0, %1;" : "=f"(r) : "f"(1.0f + e));
    return r;
}

// single-MUFU tanh (sm_75+)
__device__ __forceinline__ float tanha(float x) {
    float r;
    asm("tanh.approx.f32 %0, %1;" : "=f"(r) : "f"(x));
    return r;
}

__global__ void __launch_bounds__(TPB, 1)
lstm_kernel(const float* __restrict__ x,
            const float* __restrict__ gamma,
            const float* __restrict__ beta,
            float* __restrict__ out) {
    extern __shared__ float smem[];

    // cooperative copy of pre-permuted, pre-scaled weights into smem
    {
        const float4* src = (const float4*)g_W;
        float4* dst = (float4*)smem;
        for (int i = threadIdx.x; i < SW_FLOATS / 4; i += TPB) dst[i] = src[i];
    }
    const int w = threadIdx.x >> 5;
    const int lane = threadIdx.x & 31;       // lane = hidden unit
    float* stg = smem + SW_FLOATS + w * STG_SZ;
    for (int i = lane; i < STG_SZ; i += 32) stg[i] = 0.0f;   // h0/h1 start at zero
    __syncthreads();

    const int job = w * GRID + (int)blockIdx.x;  // balanced across 148 SMs
    if (job >= NJOBS) return;                    // only __syncwarp below: safe
    const int sBase = job * NB;

    // biases (i,f | g,o packed) stay in registers for the whole sequence
    const ulonglong2 bias0 = *reinterpret_cast<const ulonglong2*>(&g_B[4 * lane]);
    const ulonglong2 bias1 = *reinterpret_cast<const ulonglong2*>(&g_B[128 + 4 * lane]);

    // register-cached weights: KH1 rows k = 4..31 (28 rows x 16B per lane)
    ulonglong2 wc[NC];
#pragma unroll
    for (int i = 0; i < NC; i++)
        wc[i] = *(const ulonglong2*)&smem[(KH1 + 4 + i) * 128 + 4 * lane];

    // x streaming: 24 values/step; lanes 0..23 carry one (sample, dim) each
    const float* xb = x + (size_t)sBase * (T * D);
    const int s0 = lane / 6, d0 = lane - s0 * 6;
    const bool xact = lane < 24;
    const float* xp0 = xb + (size_t)s0 * (T * D) + d0;
    const int xo0 = STG_X + s0 * XP + d0;
    float xa = xact ? xp0[0] : 0.0f;

    float c0[NB], c1[NB];
#pragma unroll
    for (int s = 0; s < NB; s++) { c0[s] = 0.0f; c1[s] = 0.0f; }

    unsigned long long aIF[NB], aGO[NB];

    // 4-k chunk, weights from smem
#define CHUNK4(KB, KC, SH, STRIDE)                                                     \
    {                                                                                  \
        const ulonglong2 w0 = *(const ulonglong2*)&smem[((KB) + (KC)) * 128 + 4 * lane]; \
        const ulonglong2 w1 = *(const ulonglong2*)&smem[((KB) + (KC) + 1) * 128 + 4 * lane]; \
        const ulonglong2 w2 = *(const ulonglong2*)&smem[((KB) + (KC) + 2) * 128 + 4 * lane]; \
        const ulonglong2 w3 = *(const ulonglong2*)&smem[((KB) + (KC) + 3) * 128 + 4 * lane]; \
        _Pragma("unroll") for (int s = 0; s < NB; s++) {                               \
            const float4 v = *(const float4*)&stg[(SH) + s * (STRIDE) + (KC)];         \
            const unsigned long long e0 = dup2(v.x);                                   \
            const unsigned long long e1 = dup2(v.y);                                   \
            const unsigned long long e2 = dup2(v.z);                                   \
            const unsigned long long e3 = dup2(v.w);                                   \
            fma2(aIF[s], e0, w0.x); fma2(aGO[s], e0, w0.y);                            \
            fma2(aIF[s], e1, w1.x); fma2(aGO[s], e1, w1.y);                            \
            fma2(aIF[s], e2, w2.x); fma2(aGO[s], e2, w2.y);                            \
            fma2(aIF[s], e3, w3.x); fma2(aGO[s], e3, w3.y);                            \
        }                                                                              \
    }

    // 4-k chunk, weights from register cache wc[I0..I0+3], broadcasts from smem
#define CHUNK4R(I0, KC, SH, STRIDE)                                                    \
    {                                                                                  \
        _Pragma("unroll") for (int s = 0; s < NB; s++) {                               \
            const float4 v = *(const float4*)&stg[(SH) + s * (STRIDE) + (KC)];         \
            const unsigned long long e0 = dup2(v.x);                                   \
            const unsigned long long e1 = dup2(v.y);                                   \
            const unsigned long long e2 = dup2(v.z);                                   \
            const unsigned long long e3 = dup2(v.w);                                   \
            fma2(aIF[s], e0, wc[(I0)].x);     fma2(aGO[s], e0, wc[(I0)].y);            \
            fma2(aIF[s], e1, wc[(I0) + 1].x); fma2(aGO[s], e1, wc[(I0) + 1].y);        \
            fma2(aIF[s], e2, wc[(I0) + 2].x); fma2(aGO[s], e2, wc[(I0) + 2].y);        \
            fma2(aIF[s], e3, wc[(I0) + 3].x); fma2(aGO[s], e3, wc[(I0) + 3].y);        \
        }                                                                              \
    }

#define CHUNK2(KB, KC, SH, STRIDE)                                                     \
    {                                                                                  \
        const ulonglong2 w0 = *(const ulonglong2*)&smem[((KB) + (KC)) * 128 + 4 * lane]; \
        const ulonglong2 w1 = *(const ulonglong2*)&smem[((KB) + (KC) + 1) * 128 + 4 * lane]; \
        _Pragma("unroll") for (int s = 0; s < NB; s++) {                               \
            const float2 v = *(const float2*)&stg[(SH) + s * (STRIDE) + (KC)];         \
            const unsigned long long e0 = dup2(v.x);                                   \
            const unsigned long long e1 = dup2(v.y);                                   \
            fma2(aIF[s], e0, w0.x); fma2(aGO[s], e0, w0.y);                            \
            fma2(aIF[s], e1, w1.x); fma2(aGO[s], e1, w1.y);                            \
        }                                                                              \
    }

    // activation + undup store of h (lane = unit): 1 STS.32 per sample.
    // i,f,o: exact-path sigmoid; g and tanh(c): single-MUFU tanh.approx.
#define ACT(CC, SH)                                                                    \
    {                                                                                  \
        _Pragma("unroll") for (int s = 0; s < NB; s++) {                               \
            float si, sf, sg, so;                                                      \
            asm("mov.b64 {%0,%1}, %2;" : "=f"(si), "=f"(sf) : "l"(aIF[s]));            \
            asm("mov.b64 {%0,%1}, %2;" : "=f"(sg), "=f"(so) : "l"(aGO[s]));            \
            const float iv = sig2(si);                                                 \
            const float fv = sig2(sf);                                                 \
            const float ov = sig2(so);                                                 \
            const float gt = tanha(sg);                                                \
            const float c = fmaf(fv, CC[s], iv * gt);                                  \
            CC[s] = c;                                                                 \
            stg[(SH) + s * HP + lane] = ov * tanha(c);                                 \
        }                                                                              \
    }

    for (int t = 0; t < T; t++) {
        // publish x(t), then prefetch x(t+1)
        if (xact) stg[xo0] = xa;
        __syncwarp();
        const int tn = (t + 1 < T) ? t + 1 : t;
        if (xact) xa = xp0[(size_t)tn * D];

        // ---------------- layer 0: x (6 k) + h0 (32 k) ----------------
#pragma unroll
        for (int s = 0; s < NB; s++) { aIF[s] = bias0.x; aGO[s] = bias0.y; }
        CHUNK4(0, 0, STG_X, XP);
        CHUNK2(0, 4, STG_X, XP);
#pragma unroll
        for (int kc = 0; kc < H; kc += 4) CHUNK4(KH0, kc, STG_H0, HP);
        __syncwarp();
        ACT(c0, STG_H0);
        __syncwarp();

        // ---------------- layer 1: h0 (32 k) + h1 (32 k) ----------------
#pragma unroll
        for (int s = 0; s < NB; s++) { aIF[s] = bias1.x; aGO[s] = bias1.y; }
#pragma unroll
        for (int kc = 0; kc < H; kc += 4) CHUNK4(KI1, kc, STG_H0, HP);
        CHUNK4(KH1, 0, STG_H1, HP);                       // k 0..3 from smem
#pragma unroll
        for (int kc = 4; kc < H; kc += 4)                 // k 4..31 from registers
            CHUNK4R(kc - 4, kc, STG_H1, HP);
        __syncwarp();
        ACT(c1, STG_H1);
        __syncwarp();
    }

    // ---------------- LayerNorm over H=32 (lane = hidden unit) ----------------
    const float gam = gamma[lane];
    const float bet = beta[lane];
#pragma unroll
    for (int s = 0; s < NB; s++) {
        const float v = stg[STG_H1 + s * HP + lane];
        float sum = v;
#pragma unroll
        for (int off = 16; off > 0; off >>= 1) sum += __shfl_xor_sync(FULLMASK, sum, off);
        const float mu = sum * (1.0f / 32.0f);
        const float dd = v - mu;
        float sq = dd * dd;
#pragma unroll
        for (int off = 16; off > 0; off >>= 1) sq += __shfl_xor_sync(FULLMASK, sq, off);
        const float var = sq * (1.0f / 32.0f);
        out[(size_t)(sBase + s) * H + lane] = fmaf(dd * rsqrtf(var + 1e-5f), gam, bet);
    }
#undef CHUNK4
#undef CHUNK4R
#undef CHUNK2
#undef ACT
}

extern "C" void kernel_launch(void* const* d_in, const int* in_sizes, int n_in,
                              void* d_out, int out_size) {
    const float* x    = (const float*)d_in[0];
    const float* Wih0 = (const float*)d_in[1];
    const float* Whh0 = (const float*)d_in[2];
    const float* bih0 = (const float*)d_in[3];
    const float* bhh0 = (const float*)d_in[4];
    const float* Wih1 = (const float*)d_in[5];
    const float* Whh1 = (const float*)d_in[6];
    const float* bih1 = (const float*)d_in[7];
    const float* bhh1 = (const float*)d_in[8];
    const float* gam  = (const float*)d_in[9];
    const float* bet  = (const float*)d_in[10];
    float* out = (float*)d_out;

    cudaFuncSetAttribute(lstm_kernel, cudaFuncAttributeMaxDynamicSharedMemorySize, SMEM_BYTES);
    prep_kernel<<<1, 128>>>(Wih0, Whh0, bih0, bhh0, Wih1, Whh1, bih1, bhh1);
    lstm_kernel<<<GRID, TPB, SMEM_BYTES>>>(x, gam, bet, out);
}

// round 16
// speedup vs baseline: 1.1410x; 1.0274x over previous
#include <cuda_runtime.h>

#define FULLMASK 0xffffffffu

namespace {
constexpr int H = 32, T = 512, D = 6, B = 4096;
constexpr int NB = 4;                        // samples per warp
constexpr int NJOBS = B / NB;                // 1024 warp-jobs
constexpr int WARPS = 7;
constexpr int TPB = WARPS * 32;              // 224
constexpr int GRID = 148;                    // one block per SM
constexpr int KH0 = 6, KI1 = 38, KH1 = 70;   // k-row offsets in weight array
constexpr int SW_FLOATS = 102 * 128;         // 13056
constexpr int NC = 28;                       // register-cached k-rows (KH1 k=4..31)
constexpr int XP = 8;                        // x staging stride/sample
constexpr int HP = 32;                       // h staging stride/sample (undup)
constexpr int STG_X = 0;                     // x: 4*8 = 32 floats
constexpr int STG_H0 = 32;                   // h0: 4*32 = 128
constexpr int STG_H1 = 160;                  // h1: 4*32 = 128
constexpr int STG_SZ = 288;                  // per-warp staging floats
constexpr int SMEM_FLOATS = SW_FLOATS + WARPS * STG_SZ;  // 15072
constexpr int SMEM_BYTES = SMEM_FLOATS * 4;              // 60288
}

// weights [k][128], row r = 4*unit + gate.
// Per-gate prescale: i,f,o rows by 0.5 (sigmoid via 0.5+0.5*tanh(a/2));
// g row by 1.0 (tanh.approx directly).
__device__ __align__(16) float g_W[SW_FLOATS];
__device__ __align__(16) float g_B[256];     // [0:128) layer0, [128:256) layer1

__global__ void prep_kernel(const float* __restrict__ Wih0, const float* __restrict__ Whh0,
                            const float* __restrict__ bih0, const float* __restrict__ bhh0,
                            const float* __restrict__ Wih1, const float* __restrict__ Whh1,
                            const float* __restrict__ bih1, const float* __restrict__ bhh1) {
    int r = threadIdx.x;
    if (r >= 128) return;
    int u = r >> 2;
    int g = r & 3;
    int orig = g * H + u;                    // original gate-major row
    const float sc = (g == 2) ? 1.0f : 0.5f;
    g_B[r]       = (bih0[orig] + bhh0[orig]) * sc;
    g_B[128 + r] = (bih1[orig] + bhh1[orig]) * sc;
#pragma unroll
    for (int k = 0; k < D; k++) g_W[k * 128 + r] = Wih0[orig * D + k] * sc;
#pragma unroll
    for (int k = 0; k < H; k++) g_W[(KH0 + k) * 128 + r] = Whh0[orig * H + k] * sc;
#pragma unroll
    for (int k = 0; k < H; k++) g_W[(KI1 + k) * 128 + r] = Wih1[orig * H + k] * sc;
#pragma unroll
    for (int k = 0; k < H; k++) g_W[(KH1 + k) * 128 + r] = Whh1[orig * H + k] * sc;
}

__device__ __forceinline__ unsigned long long dup2(float v) {
    unsigned long long r;
    asm("mov.b64 %0, {%1, %1};" : "=l"(r) : "f"(v));
    return r;
}
__device__ __forceinline__ void fma2(unsigned long long& acc, unsigned long long a,
                                     unsigned long long b) {
    asm("fma.rn.f32x2 %0, %1, %2, %0;" : "+l"(acc) : "l"(a), "l"(b));
}

// single-MUFU tanh (sm_75+)
__device__ __forceinline__ float tanha(float x) {
    float r;
    asm("tanh.approx.f32 %0, %1;" : "=f"(r) : "f"(x));
    return r;
}
// sigmoid(a) where s = a/2 already (weights prescaled by 0.5)
__device__ __forceinline__ float sigt(float s) {
    return fmaf(0.5f, tanha(s), 0.5f);
}

__global__ void __launch_bounds__(TPB, 1)
lstm_kernel(const float* __restrict__ x,
            const float* __restrict__ gamma,
            const float* __restrict__ beta,
            float* __restrict__ out) {
    extern __shared__ float smem[];

    // cooperative copy of pre-permuted, pre-scaled weights into smem
    {
        const float4* src = (const float4*)g_W;
        float4* dst = (float4*)smem;
        for (int i = threadIdx.x; i < SW_FLOATS / 4; i += TPB) dst[i] = src[i];
    }
    const int w = threadIdx.x >> 5;
    const int lane = threadIdx.x & 31;       // lane = hidden unit
    float* stg = smem + SW_FLOATS + w * STG_SZ;
    for (int i = lane; i < STG_SZ; i += 32) stg[i] = 0.0f;   // h0/h1 start at zero
    __syncthreads();

    const int job = w * GRID + (int)blockIdx.x;  // balanced across 148 SMs
    if (job >= NJOBS) return;                    // only __syncwarp below: safe
    const int sBase = job * NB;

    // biases (i,f | g,o packed) stay in registers for the whole sequence
    const ulonglong2 bias0 = *reinterpret_cast<const ulonglong2*>(&g_B[4 * lane]);
    const ulonglong2 bias1 = *reinterpret_cast<const ulonglong2*>(&g_B[128 + 4 * lane]);

    // register-cached weights: KH1 rows k = 4..31 (28 rows x 16B per lane)
    ulonglong2 wc[NC];
#pragma unroll
    for (int i = 0; i < NC; i++)
        wc[i] = *(const ulonglong2*)&smem[(KH1 + 4 + i) * 128 + 4 * lane];

    // x streaming: 24 values/step; lanes 0..23 carry one (sample, dim) each
    const float* xb = x + (size_t)sBase * (T * D);
    const int s0 = lane / 6, d0 = lane - s0 * 6;
    const bool xact = lane < 24;
    const float* xp0 = xb + (size_t)s0 * (T * D) + d0;
    const int xo0 = STG_X + s0 * XP + d0;
    float xa = xact ? xp0[0] : 0.0f;

    float c0[NB], c1[NB];
#pragma unroll
    for (int s = 0; s < NB; s++) { c0[s] = 0.0f; c1[s] = 0.0f; }

    unsigned long long aIF[NB], aGO[NB];

    // 4-k chunk, weights from smem
#define CHUNK4(KB, KC, SH, STRIDE)                                                     \
    {                                                                                  \
        const ulonglong2 w0 = *(const ulonglong2*)&smem[((KB) + (KC)) * 128 + 4 * lane]; \
        const ulonglong2 w1 = *(const ulonglong2*)&smem[((KB) + (KC) + 1) * 128 + 4 * lane]; \
        const ulonglong2 w2 = *(const ulonglong2*)&smem[((KB) + (KC) + 2) * 128 + 4 * lane]; \
        const ulonglong2 w3 = *(const ulonglong2*)&smem[((KB) + (KC) + 3) * 128 + 4 * lane]; \
        _Pragma("unroll") for (int s = 0; s < NB; s++) {                               \
            const float4 v = *(const float4*)&stg[(SH) + s * (STRIDE) + (KC)];         \
            const unsigned long long e0 = dup2(v.x);                                   \
            const unsigned long long e1 = dup2(v.y);                                   \
            const unsigned long long e2 = dup2(v.z);                                   \
            const unsigned long long e3 = dup2(v.w);                                   \
            fma2(aIF[s], e0, w0.x); fma2(aGO[s], e0, w0.y);                            \
            fma2(aIF[s], e1, w1.x); fma2(aGO[s], e1, w1.y);                            \
            fma2(aIF[s], e2, w2.x); fma2(aGO[s], e2, w2.y);                            \
            fma2(aIF[s], e3, w3.x); fma2(aGO[s], e3, w3.y);                            \
        }                                                                              \
    }

    // 4-k chunk, weights from register cache wc[I0..I0+3], broadcasts from smem
#define CHUNK4R(I0, KC, SH, STRIDE)                                                    \
    {                                                                                  \
        _Pragma("unroll") for (int s = 0; s < NB; s++) {                               \
            const float4 v = *(const float4*)&stg[(SH) + s * (STRIDE) + (KC)];         \
            const unsigned long long e0 = dup2(v.x);                                   \
            const unsigned long long e1 = dup2(v.y);                                   \
            const unsigned long long e2 = dup2(v.z);                                   \
            const unsigned long long e3 = dup2(v.w);                                   \
            fma2(aIF[s], e0, wc[(I0)].x);     fma2(aGO[s], e0, wc[(I0)].y);            \
            fma2(aIF[s], e1, wc[(I0) + 1].x); fma2(aGO[s], e1, wc[(I0) + 1].y);        \
            fma2(aIF[s], e2, wc[(I0) + 2].x); fma2(aGO[s], e2, wc[(I0) + 2].y);        \
            fma2(aIF[s], e3, wc[(I0) + 3].x); fma2(aGO[s], e3, wc[(I0) + 3].y);        \
        }                                                                              \
    }

#define CHUNK2(KB, KC, SH, STRIDE)                                                     \
    {                                                                                  \
        const ulonglong2 w0 = *(const ulonglong2*)&smem[((KB) + (KC)) * 128 + 4 * lane]; \
        const ulonglong2 w1 = *(const ulonglong2*)&smem[((KB) + (KC) + 1) * 128 + 4 * lane]; \
        _Pragma("unroll") for (int s = 0; s < NB; s++) {                               \
            const float2 v = *(const float2*)&stg[(SH) + s * (STRIDE) + (KC)];         \
            const unsigned long long e0 = dup2(v.x);                                   \
            const unsigned long long e1 = dup2(v.y);                                   \
            fma2(aIF[s], e0, w0.x); fma2(aGO[s], e0, w0.y);                            \
            fma2(aIF[s], e1, w1.x); fma2(aGO[s], e1, w1.y);                            \
        }                                                                              \
    }

    // activation + undup store of h (lane = unit): 1 STS.32 per sample.
    // All gates single-MUFU: sigmoids via 0.5+0.5*tanh(a/2), tanh direct.
#define ACT(CC, SH)                                                                    \
    {                                                                                  \
        _Pragma("unroll") for (int s = 0; s < NB; s++) {                               \
            float si, sf, sg, so;                                                      \
            asm("mov.b64 {%0,%1}, %2;" : "=f"(si), "=f"(sf) : "l"(aIF[s]));            \
            asm("mov.b64 {%0,%1}, %2;" : "=f"(sg), "=f"(so) : "l"(aGO[s]));            \
            const float iv = sigt(si);                                                 \
            const float fv = sigt(sf);                                                 \
            const float ov = sigt(so);                                                 \
            const float gt = tanha(sg);                                                \
            const float c = fmaf(fv, CC[s], iv * gt);                                  \
            CC[s] = c;                                                                 \
            stg[(SH) + s * HP + lane] = ov * tanha(c);                                 \
        }                                                                              \
    }

    for (int t = 0; t < T; t++) {
        // publish x(t), then prefetch x(t+1)
        if (xact) stg[xo0] = xa;
        __syncwarp();
        const int tn = (t + 1 < T) ? t + 1 : t;
        if (xact) xa = xp0[(size_t)tn * D];

        // ---------------- layer 0: x (6 k) + h0 (32 k) ----------------
#pragma unroll
        for (int s = 0; s < NB; s++) { aIF[s] = bias0.x; aGO[s] = bias0.y; }
        CHUNK4(0, 0, STG_X, XP);
        CHUNK2(0, 4, STG_X, XP);
#pragma unroll
        for (int kc = 0; kc < H; kc += 4) CHUNK4(KH0, kc, STG_H0, HP);
        __syncwarp();
        ACT(c0, STG_H0);
        __syncwarp();

        // ---------------- layer 1: h0 (32 k) + h1 (32 k) ----------------
#pragma unroll
        for (int s = 0; s < NB; s++) { aIF[s] = bias1.x; aGO[s] = bias1.y; }
#pragma unroll
        for (int kc = 0; kc < H; kc += 4) CHUNK4(KI1, kc, STG_H0, HP);
        CHUNK4(KH1, 0, STG_H1, HP);                       // k 0..3 from smem
#pragma unroll
        for (int kc = 4; kc < H; kc += 4)                 // k 4..31 from registers
            CHUNK4R(kc - 4, kc, STG_H1, HP);
        __syncwarp();
        ACT(c1, STG_H1);
        __syncwarp();
    }

    // ---------------- LayerNorm over H=32 (lane = hidden unit) ----------------
    const float gam = gamma[lane];
    const float bet = beta[lane];
#pragma unroll
    for (int s = 0; s < NB; s++) {
        const float v = stg[STG_H1 + s * HP + lane];
        float sum = v;
#pragma unroll
        for (int off = 16; off > 0; off >>= 1) sum += __shfl_xor_sync(FULLMASK, sum, off);
        const float mu = sum * (1.0f / 32.0f);
        const float dd = v - mu;
        float sq = dd * dd;
#pragma unroll
        for (int off = 16; off > 0; off >>= 1) sq += __shfl_xor_sync(FULLMASK, sq, off);
        const float var = sq * (1.0f / 32.0f);
        out[(size_t)(sBase + s) * H + lane] = fmaf(dd * rsqrtf(var + 1e-5f), gam, bet);
    }
#undef CHUNK4
#undef CHUNK4R
#undef CHUNK2
#undef ACT
}

extern "C" void kernel_launch(void* const* d_in, const int* in_sizes, int n_in,
                              void* d_out, int out_size) {
    const float* x    = (const float*)d_in[0];
    const float* Wih0 = (const float*)d_in[1];
    const float* Whh0 = (const float*)d_in[2];
    const float* bih0 = (const float*)d_in[3];
    const float* bhh0 = (const float*)d_in[4];
    const float* Wih1 = (const float*)d_in[5];
    const float* Whh1 = (const float*)d_in[6];
    const float* bih1 = (const float*)d_in[7];
    const float* bhh1 = (const float*)d_in[8];
    const float* gam  = (const float*)d_in[9];
    const float* bet  = (const float*)d_in[10];
    float* out = (float*)d_out;

    cudaFuncSetAttribute(lstm_kernel, cudaFuncAttributeMaxDynamicSharedMemorySize, SMEM_BYTES);
    prep_kernel<<<1, 128>>>(Wih0, Whh0, bih0, bhh0, Wih1, Whh1, bih1, bhh1);
    lstm_kernel<<<GRID, TPB, SMEM_BYTES>>>(x, gam, bet, out);
}